// round 1
// baseline (speedup 1.0000x reference)
#include <cuda_runtime.h>
#include <math.h>
#include <stdint.h>

#define BDIM 4096
#define DDIM 512
#define MARGIN 0.2f

#define BM 128
#define BN 128
#define BK 16

// Scratch (no allocations allowed) -------------------------------------------
__device__ float        g_sq[BDIM];       // ||a_i||^2
__device__ float        g_dap[BDIM];      // ||a_i - p_i||^2 (squared, as in reference)
__device__ unsigned int g_min_sel[BDIM];  // min pd over diff-label & pd > d_ap (float bits)
__device__ unsigned int g_min_all[BDIM];  // min pd over diff-label            (float bits)

// ---------------------------------------------------------------------------
// Kernel A: per-row stats + init minima. One warp per row.
// ---------------------------------------------------------------------------
__global__ void row_stats_kernel(const float* __restrict__ anchor,
                                 const float* __restrict__ positive) {
    int warp = threadIdx.x >> 5;
    int lane = threadIdx.x & 31;
    int row  = blockIdx.x * 8 + warp;
    const float* a = anchor   + (size_t)row * DDIM;
    const float* p = positive + (size_t)row * DDIM;

    float s_sq = 0.f, s_ap = 0.f;
#pragma unroll
    for (int c = lane * 4; c < DDIM; c += 128) {
        float4 av = *reinterpret_cast<const float4*>(a + c);
        float4 pv = *reinterpret_cast<const float4*>(p + c);
        s_sq += av.x * av.x + av.y * av.y + av.z * av.z + av.w * av.w;
        float dx = av.x - pv.x, dy = av.y - pv.y, dz = av.z - pv.z, dw = av.w - pv.w;
        s_ap += dx * dx + dy * dy + dz * dz + dw * dw;
    }
#pragma unroll
    for (int m = 16; m > 0; m >>= 1) {
        s_sq += __shfl_xor_sync(0xffffffffu, s_sq, m);
        s_ap += __shfl_xor_sync(0xffffffffu, s_ap, m);
    }
    if (lane == 0) {
        g_sq[row]      = s_sq;
        g_dap[row]     = s_ap;
        g_min_sel[row] = 0x7F800000u;  // +inf
        g_min_all[row] = 0x7F800000u;  // +inf
    }
}

// ---------------------------------------------------------------------------
// Kernel B: fused Gram tile (fp32 SGEMM, 128x128x512) + distance + masked min
// epilogue. Grid (32, 32); 256 threads; 8x8 accumulators per thread.
// ---------------------------------------------------------------------------
__global__ __launch_bounds__(256)
void tile_kernel(const float* __restrict__ A, const int* __restrict__ labels) {
    __shared__ float As[BK][BM];
    __shared__ float Bs[BK][BN];
    __shared__ float sqj_s[BN];
    __shared__ int   labj_s[BN];

    const int i0  = blockIdx.x * BM;
    const int j0  = blockIdx.y * BN;
    const int tid = threadIdx.x;
    const int tx  = tid & 15;   // 0..15 -> j sub
    const int ty  = tid >> 4;   // 0..15 -> i sub

    if (tid < BN) {
        sqj_s[tid]  = g_sq[j0 + tid];
        labj_s[tid] = labels[j0 + tid];
    }

    float acc[8][8];
#pragma unroll
    for (int i = 0; i < 8; i++)
#pragma unroll
        for (int j = 0; j < 8; j++) acc[i][j] = 0.f;

    for (int k0 = 0; k0 < DDIM; k0 += BK) {
        // Load 128x16 A tile and 128x16 B tile (both from anchor), transposed
        // into smem. 512 float4 per tile, 256 threads -> 2 each.
#pragma unroll
        for (int l = 0; l < 2; l++) {
            int flat = tid + l * 256;        // 0..511
            int row  = flat >> 2;            // 0..127
            int c4   = (flat & 3) << 2;      // 0,4,8,12
            float4 v = *reinterpret_cast<const float4*>(A + (size_t)(i0 + row) * DDIM + k0 + c4);
            As[c4 + 0][row] = v.x; As[c4 + 1][row] = v.y;
            As[c4 + 2][row] = v.z; As[c4 + 3][row] = v.w;
            float4 w = *reinterpret_cast<const float4*>(A + (size_t)(j0 + row) * DDIM + k0 + c4);
            Bs[c4 + 0][row] = w.x; Bs[c4 + 1][row] = w.y;
            Bs[c4 + 2][row] = w.z; Bs[c4 + 3][row] = w.w;
        }
        __syncthreads();

#pragma unroll
        for (int k = 0; k < BK; k++) {
            float af[8], bf[8];
            *reinterpret_cast<float4*>(af)     = *reinterpret_cast<float4*>(&As[k][ty * 8]);
            *reinterpret_cast<float4*>(af + 4) = *reinterpret_cast<float4*>(&As[k][ty * 8 + 4]);
            *reinterpret_cast<float4*>(bf)     = *reinterpret_cast<float4*>(&Bs[k][tx * 8]);
            *reinterpret_cast<float4*>(bf + 4) = *reinterpret_cast<float4*>(&Bs[k][tx * 8 + 4]);
#pragma unroll
            for (int i = 0; i < 8; i++)
#pragma unroll
                for (int j = 0; j < 8; j++) acc[i][j] = fmaf(af[i], bf[j], acc[i][j]);
        }
        __syncthreads();
    }

    // Epilogue: distances + masked minima --------------------------------
    const float INF = __uint_as_float(0x7F800000u);
    float minsel[8], minall[8], sqi[8], dapi[8];
    int   ilab[8];
#pragma unroll
    for (int ii = 0; ii < 8; ii++) {
        int i = i0 + ty * 8 + ii;
        ilab[ii]   = labels[i];
        sqi[ii]    = g_sq[i];
        dapi[ii]   = g_dap[i];
        minsel[ii] = INF;
        minall[ii] = INF;
    }

#pragma unroll
    for (int ii = 0; ii < 8; ii++) {
#pragma unroll
        for (int jj = 0; jj < 8; jj++) {
            int   jc = tx * 8 + jj;
            float d2 = sqi[ii] + sqj_s[jc] - 2.f * acc[ii][jj];
            float pd = d2 > 0.f ? sqrtf(d2) : 0.f;
            if (labj_s[jc] != ilab[ii]) {
                minall[ii] = fminf(minall[ii], pd);
                if (pd > dapi[ii]) minsel[ii] = fminf(minsel[ii], pd);
            }
        }
    }

    // Reduce across the 16 tx-threads (consecutive lanes within a warp half).
#pragma unroll
    for (int m = 1; m < 16; m <<= 1) {
#pragma unroll
        for (int ii = 0; ii < 8; ii++) {
            minall[ii] = fminf(minall[ii], __shfl_xor_sync(0xffffffffu, minall[ii], m));
            minsel[ii] = fminf(minsel[ii], __shfl_xor_sync(0xffffffffu, minsel[ii], m));
        }
    }

    if (tx == 0) {
#pragma unroll
        for (int ii = 0; ii < 8; ii++) {
            int i = i0 + ty * 8 + ii;
            atomicMin(&g_min_all[i], __float_as_uint(minall[ii]));
            atomicMin(&g_min_sel[i], __float_as_uint(minsel[ii]));
        }
    }
}

// ---------------------------------------------------------------------------
// Kernel C: finalize — pick d_an, hinge, mean. Single block.
// ---------------------------------------------------------------------------
__global__ void finalize_kernel(float* __restrict__ out) {
    __shared__ float red[256];
    float s = 0.f;
    for (int i = threadIdx.x; i < BDIM; i += 256) {
        float ms  = __uint_as_float(g_min_sel[i]);
        float ma  = __uint_as_float(g_min_all[i]);
        float dan = isinf(ms) ? ma : ms;
        float l   = g_dap[i] - dan + MARGIN;
        s += (l > 0.f) ? l : 0.f;
    }
    red[threadIdx.x] = s;
    __syncthreads();
#pragma unroll
    for (int stride = 128; stride > 0; stride >>= 1) {
        if (threadIdx.x < stride) red[threadIdx.x] += red[threadIdx.x + stride];
        __syncthreads();
    }
    if (threadIdx.x == 0) out[0] = red[0] / (float)BDIM;
}

// ---------------------------------------------------------------------------
extern "C" void kernel_launch(void* const* d_in, const int* in_sizes, int n_in,
                              void* d_out, int out_size) {
    const float* anchor   = (const float*)d_in[0];
    const float* positive = (const float*)d_in[1];
    const int*   labels   = (const int*)d_in[2];
    float*       out      = (float*)d_out;

    row_stats_kernel<<<BDIM / 8, 256>>>(anchor, positive);
    dim3 grid(BDIM / BM, BDIM / BN);
    tile_kernel<<<grid, 256>>>(anchor, labels);
    finalize_kernel<<<1, 256>>>(out);
}

// round 5
// speedup vs baseline: 4.2752x; 4.2752x over previous
#include <cuda_runtime.h>
#include <cuda_bf16.h>
#include <math.h>
#include <stdint.h>

#define BDIM 4096
#define DDIM 512
#define MARGIN 0.2f

// ---------------------------------------------------------------------------
// Scratch (device globals; no allocations allowed)
// ---------------------------------------------------------------------------
__device__ float          g_sq[BDIM];        // ||a_i||^2
__device__ float          g_dap[BDIM];       // ||a_i - p_i||^2 (squared, as reference)
__device__ float          g_dap2[BDIM];      // (d_ap)^2
__device__ unsigned int   g_min_sel[BDIM];   // min d2 over diff-label & d2 > dap^2
__device__ unsigned int   g_min_all[BDIM];   // min d2 over diff-label
__device__ __nv_bfloat16  g_abf[BDIM * DDIM];

__device__ __forceinline__ uint32_t smem_u32(const void* p) {
    uint32_t a;
    asm("{ .reg .u64 t; cvta.to.shared.u64 t, %1; cvt.u32.u64 %0, t; }" : "=r"(a) : "l"(p));
    return a;
}

// ---------------------------------------------------------------------------
// Kernel A: per-row stats + init minima + bf16 conversion. One warp per row.
// ---------------------------------------------------------------------------
__global__ void row_stats_kernel(const float* __restrict__ anchor,
                                 const float* __restrict__ positive) {
    int warp = threadIdx.x >> 5;
    int lane = threadIdx.x & 31;
    int row  = blockIdx.x * 8 + warp;
    const float* a = anchor   + (size_t)row * DDIM;
    const float* p = positive + (size_t)row * DDIM;

    float s_sq = 0.f, s_ap = 0.f;
#pragma unroll
    for (int c = lane * 4; c < DDIM; c += 128) {
        float4 av = *reinterpret_cast<const float4*>(a + c);
        float4 pv = *reinterpret_cast<const float4*>(p + c);
        s_sq += av.x * av.x + av.y * av.y + av.z * av.z + av.w * av.w;
        float dx = av.x - pv.x, dy = av.y - pv.y, dz = av.z - pv.z, dw = av.w - pv.w;
        s_ap += dx * dx + dy * dy + dz * dz + dw * dw;
        __nv_bfloat162 b0 = __floats2bfloat162_rn(av.x, av.y);
        __nv_bfloat162 b1 = __floats2bfloat162_rn(av.z, av.w);
        uint2 packed = make_uint2(*reinterpret_cast<uint32_t*>(&b0),
                                  *reinterpret_cast<uint32_t*>(&b1));
        *reinterpret_cast<uint2*>(&g_abf[(size_t)row * DDIM + c]) = packed;
    }
#pragma unroll
    for (int m = 16; m > 0; m >>= 1) {
        s_sq += __shfl_xor_sync(0xffffffffu, s_sq, m);
        s_ap += __shfl_xor_sync(0xffffffffu, s_ap, m);
    }
    if (lane == 0) {
        g_sq[row]      = s_sq;
        g_dap[row]     = s_ap;
        g_dap2[row]    = s_ap * s_ap;
        g_min_sel[row] = 0x7F800000u;  // +inf
        g_min_all[row] = 0x7F800000u;  // +inf
    }
}

// ---------------------------------------------------------------------------
// Kernel B: bf16 HMMA Gram tile (128x128x512) + fused masked-min epilogue.
// 256 threads / 8 warps (4 x 2). Warp tile 32(M) x 64(N). BK=32.
// Double-buffered smem via cp.async; xor-swizzled for conflict-free ldmatrix.
// ---------------------------------------------------------------------------
#define NSTEPS (DDIM / 32)   // 16

__global__ __launch_bounds__(256)
void tile_kernel(const int* __restrict__ labels) {
    __shared__ __align__(1024) char smA[2][128 * 64];  // 128 rows x 32 bf16
    __shared__ __align__(1024) char smB[2][128 * 64];
    __shared__ float sqj_s[128];
    __shared__ int   labj_s[128];

    const int tid    = threadIdx.x;
    const int wid    = tid >> 5;
    const int lane   = tid & 31;
    const int warp_m = wid & 3;    // 0..3 -> M offset 32*warp_m
    const int warp_n = wid >> 2;   // 0..1 -> N offset 64*warp_n
    const int i0     = blockIdx.x * 128;
    const int j0     = blockIdx.y * 128;

    if (tid < 128) {
        sqj_s[tid]  = g_sq[j0 + tid];
        labj_s[tid] = labels[j0 + tid];
    }

    const uint32_t smA_u[2] = { smem_u32(smA[0]), smem_u32(smA[1]) };
    const uint32_t smB_u[2] = { smem_u32(smB[0]), smem_u32(smB[1]) };

    // Per-thread global-load assignment: row = tid>>1, two 16B chunks.
    const int ld_row = tid >> 1;
    const int ld_kc0 = (tid & 1) * 2;  // chunks {0,1} or {2,3}

    auto issue_loads = [&](int stage, int k0) {
        const __nv_bfloat16* srcA = g_abf + (size_t)(i0 + ld_row) * DDIM + k0;
        const __nv_bfloat16* srcB = g_abf + (size_t)(j0 + ld_row) * DDIM + k0;
#pragma unroll
        for (int l = 0; l < 2; l++) {
            int kc = ld_kc0 + l;
            uint32_t off = (uint32_t)(ld_row * 64 + ((kc ^ (ld_row & 3)) << 4));
            asm volatile("cp.async.cg.shared.global [%0], [%1], 16;"
                         :: "r"(smA_u[stage] + off), "l"(srcA + kc * 8) : "memory");
            asm volatile("cp.async.cg.shared.global [%0], [%1], 16;"
                         :: "r"(smB_u[stage] + off), "l"(srcB + kc * 8) : "memory");
        }
        asm volatile("cp.async.commit_group;" ::: "memory");
    };

    float acc[2][8][4];
#pragma unroll
    for (int mf = 0; mf < 2; mf++)
#pragma unroll
        for (int nf = 0; nf < 8; nf++)
#pragma unroll
            for (int c = 0; c < 4; c++) acc[mf][nf][c] = 0.f;

    issue_loads(0, 0);

    for (int it = 0; it < NSTEPS; it++) {
        const int buf = it & 1;
        if (it + 1 < NSTEPS) {
            issue_loads(buf ^ 1, (it + 1) * 32);
            asm volatile("cp.async.wait_group 1;" ::: "memory");
        } else {
            asm volatile("cp.async.wait_group 0;" ::: "memory");
        }
        __syncthreads();

        // 2 k16 steps within the BK=32 tile
#pragma unroll
        for (int s = 0; s < 2; s++) {
            // A frags: 2 ldmatrix.x4 (one per 16-row m-frag)
            uint32_t a[2][4];
#pragma unroll
            for (int mf = 0; mf < 2; mf++) {
                int row = warp_m * 32 + mf * 16 + ((lane >> 3) & 1) * 8 + (lane & 7);
                int kc  = 2 * s + (lane >> 4);
                uint32_t addr = smA_u[buf] + row * 64 + ((kc ^ (row & 3)) << 4);
                asm volatile("ldmatrix.sync.aligned.m8n8.x4.shared.b16 {%0,%1,%2,%3}, [%4];"
                             : "=r"(a[mf][0]), "=r"(a[mf][1]), "=r"(a[mf][2]), "=r"(a[mf][3])
                             : "r"(addr));
            }
            // B frags: 4 ldmatrix.x4, each covers 16 n-rows x 16 k
            uint32_t b[4][4];
#pragma unroll
            for (int p = 0; p < 4; p++) {
                int row = warp_n * 64 + p * 16 + ((lane >> 3) & 1) * 8 + (lane & 7);
                int kc  = 2 * s + (lane >> 4);
                uint32_t addr = smB_u[buf] + row * 64 + ((kc ^ (row & 3)) << 4);
                asm volatile("ldmatrix.sync.aligned.m8n8.x4.shared.b16 {%0,%1,%2,%3}, [%4];"
                             : "=r"(b[p][0]), "=r"(b[p][1]), "=r"(b[p][2]), "=r"(b[p][3])
                             : "r"(addr));
            }
#pragma unroll
            for (int mf = 0; mf < 2; mf++) {
#pragma unroll
                for (int nf = 0; nf < 8; nf++) {
                    int p  = nf >> 1;
                    int lo = (nf & 1);        // even nf -> regs {0,2}; odd -> {1,3}
                    asm volatile(
                        "mma.sync.aligned.m16n8k16.row.col.f32.bf16.bf16.f32 "
                        "{%0,%1,%2,%3}, {%4,%5,%6,%7}, {%8,%9}, {%0,%1,%2,%3};"
                        : "+f"(acc[mf][nf][0]), "+f"(acc[mf][nf][1]),
                          "+f"(acc[mf][nf][2]), "+f"(acc[mf][nf][3])
                        : "r"(a[mf][0]), "r"(a[mf][1]), "r"(a[mf][2]), "r"(a[mf][3]),
                          "r"(b[p][lo]), "r"(b[p][lo + 2]));
                }
            }
        }
        __syncthreads();
    }

    // Epilogue ---------------------------------------------------------------
    // Accumulator layout (m16n8): c0:(r, 2c) c1:(r, 2c+1) c2:(r+8, 2c) c3:(r+8, 2c+1)
    // with r = lane>>2, c = lane&3.
    const float INF = __uint_as_float(0x7F800000u);
#pragma unroll
    for (int mf = 0; mf < 2; mf++) {
        int r0 = warp_m * 32 + mf * 16 + (lane >> 2);  // local row for c0/c1
        int r1 = r0 + 8;                               // local row for c2/c3
        int gi0 = i0 + r0, gi1 = i0 + r1;
        int   lab0 = labels[gi0],  lab1 = labels[gi1];
        float sqi0 = g_sq[gi0],    sqi1 = g_sq[gi1];
        float dp0  = g_dap2[gi0],  dp1  = g_dap2[gi1];
        float ma0 = INF, ms0 = INF, ma1 = INF, ms1 = INF;

#pragma unroll
        for (int nf = 0; nf < 8; nf++) {
#pragma unroll
            for (int cc = 0; cc < 2; cc++) {
                int jloc = warp_n * 64 + nf * 8 + (lane & 3) * 2 + cc;
                float sqj = sqj_s[jloc];
                int   lbj = labj_s[jloc];
                float d2a = fmaxf(sqi0 + sqj - 2.f * acc[mf][nf][cc], 0.f);
                if (lbj != lab0) {
                    ma0 = fminf(ma0, d2a);
                    if (d2a > dp0) ms0 = fminf(ms0, d2a);
                }
                float d2b = fmaxf(sqi1 + sqj - 2.f * acc[mf][nf][cc + 2], 0.f);
                if (lbj != lab1) {
                    ma1 = fminf(ma1, d2b);
                    if (d2b > dp1) ms1 = fminf(ms1, d2b);
                }
            }
        }
        // Reduce across the 4 lanes that share each row (lane groups of 4)
#pragma unroll
        for (int m = 1; m < 4; m <<= 1) {
            ma0 = fminf(ma0, __shfl_xor_sync(0xffffffffu, ma0, m));
            ms0 = fminf(ms0, __shfl_xor_sync(0xffffffffu, ms0, m));
            ma1 = fminf(ma1, __shfl_xor_sync(0xffffffffu, ma1, m));
            ms1 = fminf(ms1, __shfl_xor_sync(0xffffffffu, ms1, m));
        }
        if ((lane & 3) == 0) {
            atomicMin(&g_min_all[gi0], __float_as_uint(ma0));
            atomicMin(&g_min_sel[gi0], __float_as_uint(ms0));
            atomicMin(&g_min_all[gi1], __float_as_uint(ma1));
            atomicMin(&g_min_sel[gi1], __float_as_uint(ms1));
        }
    }
}

// ---------------------------------------------------------------------------
// Kernel C: finalize — d_an = sqrt(selected min d2), hinge, mean.
// ---------------------------------------------------------------------------
__global__ void finalize_kernel(float* __restrict__ out) {
    __shared__ float red[256];
    float s = 0.f;
    for (int i = threadIdx.x; i < BDIM; i += 256) {
        float ms   = __uint_as_float(g_min_sel[i]);
        float ma   = __uint_as_float(g_min_all[i]);
        float dan2 = isinf(ms) ? ma : ms;
        float dan  = sqrtf(dan2);
        float l    = g_dap[i] - dan + MARGIN;
        s += (l > 0.f) ? l : 0.f;
    }
    red[threadIdx.x] = s;
    __syncthreads();
#pragma unroll
    for (int stride = 128; stride > 0; stride >>= 1) {
        if (threadIdx.x < stride) red[threadIdx.x] += red[threadIdx.x + stride];
        __syncthreads();
    }
    if (threadIdx.x == 0) out[0] = red[0] / (float)BDIM;
}

// ---------------------------------------------------------------------------
extern "C" void kernel_launch(void* const* d_in, const int* in_sizes, int n_in,
                              void* d_out, int out_size) {
    const float* anchor   = (const float*)d_in[0];
    const float* positive = (const float*)d_in[1];
    const int*   labels   = (const int*)d_in[2];
    float*       out      = (float*)d_out;

    row_stats_kernel<<<BDIM / 8, 256>>>(anchor, positive);
    dim3 grid(BDIM / 128, BDIM / 128);
    tile_kernel<<<grid, 256>>>(labels);
    finalize_kernel<<<1, 256>>>(out);
}

// round 6
// speedup vs baseline: 5.2933x; 1.2382x over previous
#include <cuda_runtime.h>
#include <cuda_bf16.h>
#include <math.h>
#include <stdint.h>

#define BDIM 4096
#define DDIM 512
#define MARGIN 0.2f

#define NTILE   32                   // 4096/128
#define NBLK    (NTILE * (NTILE+1) / 2)   // 528 upper-triangle tiles
#define NSTEPS  (DDIM / 32)          // 16
#define STAGE_BYTES 16384            // A(8K) + B(8K) per stage
#define DYN_SMEM (3 * STAGE_BYTES)

// ---------------------------------------------------------------------------
__device__ float          g_sq[BDIM];
__device__ float          g_dap[BDIM];
__device__ float          g_dap2[BDIM];
__device__ unsigned int   g_min_sel[BDIM];
__device__ unsigned int   g_min_all[BDIM];
__device__ __nv_bfloat16  g_abf[BDIM * DDIM];

__device__ __forceinline__ uint32_t smem_u32(const void* p) {
    uint32_t a;
    asm("{ .reg .u64 t; cvta.to.shared.u64 t, %1; cvt.u32.u64 %0, t; }" : "=r"(a) : "l"(p));
    return a;
}

// ---------------------------------------------------------------------------
// Kernel A: per-row stats + init minima + bf16 conversion. One warp per row.
// ---------------------------------------------------------------------------
__global__ __launch_bounds__(512)
void row_stats_kernel(const float* __restrict__ anchor,
                      const float* __restrict__ positive) {
    int warp = threadIdx.x >> 5;
    int lane = threadIdx.x & 31;
    int row  = blockIdx.x * 16 + warp;
    const float* a = anchor   + (size_t)row * DDIM;
    const float* p = positive + (size_t)row * DDIM;

    float s_sq = 0.f, s_ap = 0.f;
#pragma unroll
    for (int c = lane * 4; c < DDIM; c += 128) {
        float4 av = *reinterpret_cast<const float4*>(a + c);
        float4 pv = *reinterpret_cast<const float4*>(p + c);
        s_sq += av.x * av.x + av.y * av.y + av.z * av.z + av.w * av.w;
        float dx = av.x - pv.x, dy = av.y - pv.y, dz = av.z - pv.z, dw = av.w - pv.w;
        s_ap += dx * dx + dy * dy + dz * dz + dw * dw;
        __nv_bfloat162 b0 = __floats2bfloat162_rn(av.x, av.y);
        __nv_bfloat162 b1 = __floats2bfloat162_rn(av.z, av.w);
        uint2 packed = make_uint2(*reinterpret_cast<uint32_t*>(&b0),
                                  *reinterpret_cast<uint32_t*>(&b1));
        *reinterpret_cast<uint2*>(&g_abf[(size_t)row * DDIM + c]) = packed;
    }
#pragma unroll
    for (int m = 16; m > 0; m >>= 1) {
        s_sq += __shfl_xor_sync(0xffffffffu, s_sq, m);
        s_ap += __shfl_xor_sync(0xffffffffu, s_ap, m);
    }
    if (lane == 0) {
        g_sq[row]      = s_sq;
        g_dap[row]     = s_ap;
        g_dap2[row]    = s_ap * s_ap;
        g_min_sel[row] = 0x7F800000u;
        g_min_all[row] = 0x7F800000u;
    }
}

// ---------------------------------------------------------------------------
// Kernel B: symmetric bf16 HMMA Gram tile (128x128x512), upper-triangle only,
// with fused row-side AND column-side masked-min epilogue.
// 256 threads / 8 warps (4 x 2). Warp tile 32(M) x 64(N). BK=32, 3-stage.
// ---------------------------------------------------------------------------
__global__ __launch_bounds__(256)
void tile_kernel(const int* __restrict__ labels) {
    extern __shared__ __align__(1024) char dsm[];
    __shared__ float sqj_s[128];
    __shared__ float dpj_s[128];
    __shared__ int   labj_s[128];

    const int tid    = threadIdx.x;
    const int wid    = tid >> 5;
    const int lane   = tid & 31;
    const int warp_m = wid & 3;
    const int warp_n = wid >> 2;

    // Linear block id -> upper-triangle (bi, bj), bi <= bj
    int t = blockIdx.x;
    int bi = 0;
    {
        int rem = t;
        while (rem >= NTILE - bi) { rem -= NTILE - bi; bi++; }
        t = bi + rem;  // bj
    }
    const int bj = t;
    const int i0 = bi * 128;
    const int j0 = bj * 128;

    if (tid < 128) {
        sqj_s[tid]  = g_sq[j0 + tid];
        dpj_s[tid]  = g_dap2[j0 + tid];
        labj_s[tid] = labels[j0 + tid];
    }

    uint32_t stg_u[3];
#pragma unroll
    for (int s = 0; s < 3; s++) stg_u[s] = smem_u32(dsm) + s * STAGE_BYTES;

    const int ld_row = tid >> 1;
    const int ld_kc0 = (tid & 1) * 2;

    auto issue_loads = [&](int stage, int k0) {
        const __nv_bfloat16* srcA = g_abf + (size_t)(i0 + ld_row) * DDIM + k0;
        const __nv_bfloat16* srcB = g_abf + (size_t)(j0 + ld_row) * DDIM + k0;
#pragma unroll
        for (int l = 0; l < 2; l++) {
            int kc = ld_kc0 + l;
            uint32_t off = (uint32_t)(ld_row * 64 + ((kc ^ (ld_row & 3)) << 4));
            asm volatile("cp.async.cg.shared.global [%0], [%1], 16;"
                         :: "r"(stg_u[stage] + off), "l"(srcA + kc * 8) : "memory");
            asm volatile("cp.async.cg.shared.global [%0], [%1], 16;"
                         :: "r"(stg_u[stage] + 8192 + off), "l"(srcB + kc * 8) : "memory");
        }
        asm volatile("cp.async.commit_group;" ::: "memory");
    };

    float acc[2][8][4];
#pragma unroll
    for (int mf = 0; mf < 2; mf++)
#pragma unroll
        for (int nf = 0; nf < 8; nf++)
#pragma unroll
            for (int c = 0; c < 4; c++) acc[mf][nf][c] = 0.f;

    issue_loads(0, 0);
    issue_loads(1, 32);

    int buf = 0;
    for (int it = 0; it < NSTEPS; it++) {
        if (it < NSTEPS - 1) asm volatile("cp.async.wait_group 1;" ::: "memory");
        else                 asm volatile("cp.async.wait_group 0;" ::: "memory");
        __syncthreads();
        if (it + 2 < NSTEPS) {
            int nstage = buf + 2; if (nstage >= 3) nstage -= 3;
            issue_loads(nstage, (it + 2) * 32);
        }

        const uint32_t a_base = stg_u[buf];
        const uint32_t b_base = stg_u[buf] + 8192;
#pragma unroll
        for (int s = 0; s < 2; s++) {
            uint32_t a[2][4];
#pragma unroll
            for (int mf = 0; mf < 2; mf++) {
                int row = warp_m * 32 + mf * 16 + ((lane >> 3) & 1) * 8 + (lane & 7);
                int kc  = 2 * s + (lane >> 4);
                uint32_t addr = a_base + row * 64 + ((kc ^ (row & 3)) << 4);
                asm volatile("ldmatrix.sync.aligned.m8n8.x4.shared.b16 {%0,%1,%2,%3}, [%4];"
                             : "=r"(a[mf][0]), "=r"(a[mf][1]), "=r"(a[mf][2]), "=r"(a[mf][3])
                             : "r"(addr));
            }
            uint32_t b[4][4];
#pragma unroll
            for (int p = 0; p < 4; p++) {
                int row = warp_n * 64 + p * 16 + ((lane >> 3) & 1) * 8 + (lane & 7);
                int kc  = 2 * s + (lane >> 4);
                uint32_t addr = b_base + row * 64 + ((kc ^ (row & 3)) << 4);
                asm volatile("ldmatrix.sync.aligned.m8n8.x4.shared.b16 {%0,%1,%2,%3}, [%4];"
                             : "=r"(b[p][0]), "=r"(b[p][1]), "=r"(b[p][2]), "=r"(b[p][3])
                             : "r"(addr));
            }
#pragma unroll
            for (int mf = 0; mf < 2; mf++) {
#pragma unroll
                for (int nf = 0; nf < 8; nf++) {
                    int p  = nf >> 1;
                    int lo = (nf & 1);
                    asm volatile(
                        "mma.sync.aligned.m16n8k16.row.col.f32.bf16.bf16.f32 "
                        "{%0,%1,%2,%3}, {%4,%5,%6,%7}, {%8,%9}, {%0,%1,%2,%3};"
                        : "+f"(acc[mf][nf][0]), "+f"(acc[mf][nf][1]),
                          "+f"(acc[mf][nf][2]), "+f"(acc[mf][nf][3])
                        : "r"(a[mf][0]), "r"(a[mf][1]), "r"(a[mf][2]), "r"(a[mf][3]),
                          "r"(b[p][lo]), "r"(b[p][lo + 2]));
                }
            }
        }
        __syncthreads();
        buf++; if (buf == 3) buf = 0;
    }

    // Epilogue ---------------------------------------------------------------
    // acc layout (m16n8): c0:(r,2c) c1:(r,2c+1) c2:(r+8,2c) c3:(r+8,2c+1),
    // r = lane>>2, c = lane&3.
    const float INF = __uint_as_float(0x7F800000u);

    // Column-side minima: per thread, 16 columns (nf x cc), min over its 4 rows.
    float colall[8][2], colsel[8][2];
#pragma unroll
    for (int nf = 0; nf < 8; nf++) { colall[nf][0] = colall[nf][1] = INF;
                                     colsel[nf][0] = colsel[nf][1] = INF; }

#pragma unroll
    for (int mf = 0; mf < 2; mf++) {
        int r0 = warp_m * 32 + mf * 16 + (lane >> 2);
        int r1 = r0 + 8;
        int gi0 = i0 + r0, gi1 = i0 + r1;
        int   lab0 = labels[gi0],  lab1 = labels[gi1];
        float sqi0 = g_sq[gi0],    sqi1 = g_sq[gi1];
        float dp0  = g_dap2[gi0],  dp1  = g_dap2[gi1];
        float ma0 = INF, ms0 = INF, ma1 = INF, ms1 = INF;

#pragma unroll
        for (int nf = 0; nf < 8; nf++) {
#pragma unroll
            for (int cc = 0; cc < 2; cc++) {
                int jloc = warp_n * 64 + nf * 8 + (lane & 3) * 2 + cc;
                float sqj = sqj_s[jloc];
                float dpj = dpj_s[jloc];
                int   lbj = labj_s[jloc];
                float d2a = fmaxf(sqi0 + sqj - 2.f * acc[mf][nf][cc], 0.f);
                float d2b = fmaxf(sqi1 + sqj - 2.f * acc[mf][nf][cc + 2], 0.f);
                if (lbj != lab0) {
                    ma0 = fminf(ma0, d2a);
                    if (d2a > dp0) ms0 = fminf(ms0, d2a);
                    // column side (row j vs i=gi0); label mask symmetric
                    colall[nf][cc] = fminf(colall[nf][cc], d2a);
                    if (d2a > dpj) colsel[nf][cc] = fminf(colsel[nf][cc], d2a);
                }
                if (lbj != lab1) {
                    ma1 = fminf(ma1, d2b);
                    if (d2b > dp1) ms1 = fminf(ms1, d2b);
                    colall[nf][cc] = fminf(colall[nf][cc], d2b);
                    if (d2b > dpj) colsel[nf][cc] = fminf(colsel[nf][cc], d2b);
                }
            }
        }
#pragma unroll
        for (int m = 1; m < 4; m <<= 1) {
            ma0 = fminf(ma0, __shfl_xor_sync(0xffffffffu, ma0, m));
            ms0 = fminf(ms0, __shfl_xor_sync(0xffffffffu, ms0, m));
            ma1 = fminf(ma1, __shfl_xor_sync(0xffffffffu, ma1, m));
            ms1 = fminf(ms1, __shfl_xor_sync(0xffffffffu, ms1, m));
        }
        if ((lane & 3) == 0) {
            atomicMin(&g_min_all[gi0], __float_as_uint(ma0));
            atomicMin(&g_min_sel[gi0], __float_as_uint(ms0));
            atomicMin(&g_min_all[gi1], __float_as_uint(ma1));
            atomicMin(&g_min_sel[gi1], __float_as_uint(ms1));
        }
    }

    // Reduce column minima over the 8 lane-groups (rows) within the warp.
#pragma unroll
    for (int nf = 0; nf < 8; nf++)
#pragma unroll
        for (int cc = 0; cc < 2; cc++) {
#pragma unroll
            for (int m = 4; m < 32; m <<= 1) {
                colall[nf][cc] = fminf(colall[nf][cc], __shfl_xor_sync(0xffffffffu, colall[nf][cc], m));
                colsel[nf][cc] = fminf(colsel[nf][cc], __shfl_xor_sync(0xffffffffu, colsel[nf][cc], m));
            }
        }
    if (lane < 4) {
#pragma unroll
        for (int nf = 0; nf < 8; nf++)
#pragma unroll
            for (int cc = 0; cc < 2; cc++) {
                int gj = j0 + warp_n * 64 + nf * 8 + lane * 2 + cc;
                atomicMin(&g_min_all[gj], __float_as_uint(colall[nf][cc]));
                atomicMin(&g_min_sel[gj], __float_as_uint(colsel[nf][cc]));
            }
    }
}

// ---------------------------------------------------------------------------
// Kernel C: finalize
// ---------------------------------------------------------------------------
__global__ void finalize_kernel(float* __restrict__ out) {
    __shared__ float red[256];
    float s = 0.f;
    for (int i = threadIdx.x; i < BDIM; i += 256) {
        float ms   = __uint_as_float(g_min_sel[i]);
        float ma   = __uint_as_float(g_min_all[i]);
        float dan2 = isinf(ms) ? ma : ms;
        float dan  = sqrtf(dan2);
        float l    = g_dap[i] - dan + MARGIN;
        s += (l > 0.f) ? l : 0.f;
    }
    red[threadIdx.x] = s;
    __syncthreads();
#pragma unroll
    for (int stride = 128; stride > 0; stride >>= 1) {
        if (threadIdx.x < stride) red[threadIdx.x] += red[threadIdx.x + stride];
        __syncthreads();
    }
    if (threadIdx.x == 0) out[0] = red[0] / (float)BDIM;
}

// ---------------------------------------------------------------------------
extern "C" void kernel_launch(void* const* d_in, const int* in_sizes, int n_in,
                              void* d_out, int out_size) {
    const float* anchor   = (const float*)d_in[0];
    const float* positive = (const float*)d_in[1];
    const int*   labels   = (const int*)d_in[2];
    float*       out      = (float*)d_out;

    cudaFuncSetAttribute(tile_kernel, cudaFuncAttributeMaxDynamicSharedMemorySize, DYN_SMEM);

    row_stats_kernel<<<BDIM / 16, 512>>>(anchor, positive);
    tile_kernel<<<NBLK, 256, DYN_SMEM>>>(labels);
    finalize_kernel<<<1, 256>>>(out);
}

// round 7
// speedup vs baseline: 6.2811x; 1.1866x over previous
#include <cuda_runtime.h>
#include <cuda_bf16.h>
#include <math.h>
#include <stdint.h>

#define BDIM 4096
#define DDIM 512
#define MARGIN 0.2f

#define NTILE   32
#define NBLK    (NTILE * (NTILE + 1) / 2)  // 528
#define NSTEPS  (DDIM / 32)                // 16
#define STAGE_BYTES 16384                  // A(8K) + B(8K)
#define DYN_SMEM (4 * STAGE_BYTES)         // 64KB, 4 stages

// ---------------------------------------------------------------------------
__device__ float          g_sq[BDIM];
__device__ float          g_dap[BDIM];
__device__ float          g_dap2[BDIM];
__device__ unsigned int   g_min_sel[BDIM];
__device__ unsigned int   g_min_all[BDIM];
__device__ __nv_bfloat16  g_abf[BDIM * DDIM];

__device__ __forceinline__ uint32_t smem_u32(const void* p) {
    uint32_t a;
    asm("{ .reg .u64 t; cvta.to.shared.u64 t, %1; cvt.u32.u64 %0, t; }" : "=r"(a) : "l"(p));
    return a;
}

// Conflict-free layout: 2 logical rows per 128B line; chunk (0..7) XOR line.
// addr(row, kc) for kc in 0..3 (16B chunks of the 64B logical row).
__device__ __forceinline__ uint32_t sw_off(int row, int kc) {
    int line  = row >> 1;
    int chunk = (((row & 1) << 2) | kc) ^ (line & 7);
    return (uint32_t)(line * 128 + chunk * 16);
}

// ---------------------------------------------------------------------------
// Kernel A: per-row stats + init minima + bf16 conversion. One warp per row.
// ---------------------------------------------------------------------------
__global__ __launch_bounds__(512)
void row_stats_kernel(const float* __restrict__ anchor,
                      const float* __restrict__ positive) {
    int warp = threadIdx.x >> 5;
    int lane = threadIdx.x & 31;
    int row  = blockIdx.x * 16 + warp;
    const float* a = anchor   + (size_t)row * DDIM;
    const float* p = positive + (size_t)row * DDIM;

    float s_sq = 0.f, s_ap = 0.f;
#pragma unroll
    for (int c = lane * 4; c < DDIM; c += 128) {
        float4 av = *reinterpret_cast<const float4*>(a + c);
        float4 pv = *reinterpret_cast<const float4*>(p + c);
        s_sq += av.x * av.x + av.y * av.y + av.z * av.z + av.w * av.w;
        float dx = av.x - pv.x, dy = av.y - pv.y, dz = av.z - pv.z, dw = av.w - pv.w;
        s_ap += dx * dx + dy * dy + dz * dz + dw * dw;
        __nv_bfloat162 b0 = __floats2bfloat162_rn(av.x, av.y);
        __nv_bfloat162 b1 = __floats2bfloat162_rn(av.z, av.w);
        uint2 packed = make_uint2(*reinterpret_cast<uint32_t*>(&b0),
                                  *reinterpret_cast<uint32_t*>(&b1));
        *reinterpret_cast<uint2*>(&g_abf[(size_t)row * DDIM + c]) = packed;
    }
#pragma unroll
    for (int m = 16; m > 0; m >>= 1) {
        s_sq += __shfl_xor_sync(0xffffffffu, s_sq, m);
        s_ap += __shfl_xor_sync(0xffffffffu, s_ap, m);
    }
    if (lane == 0) {
        g_sq[row]      = s_sq;
        g_dap[row]     = s_ap;
        g_dap2[row]    = s_ap * s_ap;
        g_min_sel[row] = 0x7F800000u;
        g_min_all[row] = 0x7F800000u;
    }
}

// ---------------------------------------------------------------------------
// Kernel B: symmetric bf16 HMMA Gram tile (128x128x512), upper triangle only,
// fused row+column masked-min epilogue. 256 thr / 8 warps; warp tile 32x64.
// BK=32, 4-stage cp.async ring; 2 CTAs/SM (reg-capped).
// ---------------------------------------------------------------------------
__global__ __launch_bounds__(256, 2)
void tile_kernel(const int* __restrict__ labels) {
    extern __shared__ __align__(1024) char dsm[];
    __shared__ float sqj_s[128];
    __shared__ float dpj_s[128];
    __shared__ int   labj_s[128];

    const int tid    = threadIdx.x;
    const int wid    = tid >> 5;
    const int lane   = tid & 31;
    const int warp_m = wid & 3;
    const int warp_n = wid >> 2;

    // Linear block id -> (bi, bj), bi <= bj
    int t = blockIdx.x;
    int bi = 0;
    {
        int rem = t;
        while (rem >= NTILE - bi) { rem -= NTILE - bi; bi++; }
        t = bi + rem;
    }
    const int bj = t;
    const int i0 = bi * 128;
    const int j0 = bj * 128;

    if (tid < 128) {
        sqj_s[tid]  = g_sq[j0 + tid];
        dpj_s[tid]  = g_dap2[j0 + tid];
        labj_s[tid] = labels[j0 + tid];
    }

    const uint32_t dsm_u = smem_u32(dsm);

    const int ld_row = tid >> 1;
    const int ld_kc0 = (tid & 1) * 2;

    auto issue_loads = [&](int stage, int k0) {
        const __nv_bfloat16* srcA = g_abf + (size_t)(i0 + ld_row) * DDIM + k0;
        const __nv_bfloat16* srcB = g_abf + (size_t)(j0 + ld_row) * DDIM + k0;
        uint32_t sbase = dsm_u + stage * STAGE_BYTES;
#pragma unroll
        for (int l = 0; l < 2; l++) {
            int kc = ld_kc0 + l;
            uint32_t off = sw_off(ld_row, kc);
            asm volatile("cp.async.cg.shared.global [%0], [%1], 16;"
                         :: "r"(sbase + off), "l"(srcA + kc * 8) : "memory");
            asm volatile("cp.async.cg.shared.global [%0], [%1], 16;"
                         :: "r"(sbase + 8192 + off), "l"(srcB + kc * 8) : "memory");
        }
        asm volatile("cp.async.commit_group;" ::: "memory");
    };

    float acc[2][8][4];
#pragma unroll
    for (int mf = 0; mf < 2; mf++)
#pragma unroll
        for (int nf = 0; nf < 8; nf++)
#pragma unroll
            for (int c = 0; c < 4; c++) acc[mf][nf][c] = 0.f;

    issue_loads(0, 0);
    issue_loads(1, 32);
    issue_loads(2, 64);

    for (int it = 0; it < NSTEPS; it++) {
        const int buf = it & 3;
        if (it < NSTEPS - 2)      asm volatile("cp.async.wait_group 2;" ::: "memory");
        else if (it == NSTEPS - 2) asm volatile("cp.async.wait_group 1;" ::: "memory");
        else                       asm volatile("cp.async.wait_group 0;" ::: "memory");
        __syncthreads();
        if (it + 3 < NSTEPS) issue_loads((it + 3) & 3, (it + 3) * 32);

        const uint32_t a_base = dsm_u + buf * STAGE_BYTES;
        const uint32_t b_base = a_base + 8192;
#pragma unroll
        for (int s = 0; s < 2; s++) {
            const int kc = 2 * s + (lane >> 4);
            uint32_t a[2][4];
#pragma unroll
            for (int mf = 0; mf < 2; mf++) {
                int row = warp_m * 32 + mf * 16 + ((lane >> 3) & 1) * 8 + (lane & 7);
                uint32_t addr = a_base + sw_off(row, kc);
                asm volatile("ldmatrix.sync.aligned.m8n8.x4.shared.b16 {%0,%1,%2,%3}, [%4];"
                             : "=r"(a[mf][0]), "=r"(a[mf][1]), "=r"(a[mf][2]), "=r"(a[mf][3])
                             : "r"(addr));
            }
            uint32_t b[4][4];
#pragma unroll
            for (int p = 0; p < 4; p++) {
                int row = warp_n * 64 + p * 16 + ((lane >> 3) & 1) * 8 + (lane & 7);
                uint32_t addr = b_base + sw_off(row, kc);
                asm volatile("ldmatrix.sync.aligned.m8n8.x4.shared.b16 {%0,%1,%2,%3}, [%4];"
                             : "=r"(b[p][0]), "=r"(b[p][1]), "=r"(b[p][2]), "=r"(b[p][3])
                             : "r"(addr));
            }
#pragma unroll
            for (int mf = 0; mf < 2; mf++) {
#pragma unroll
                for (int nf = 0; nf < 8; nf++) {
                    int p  = nf >> 1;
                    int lo = (nf & 1);
                    asm volatile(
                        "mma.sync.aligned.m16n8k16.row.col.f32.bf16.bf16.f32 "
                        "{%0,%1,%2,%3}, {%4,%5,%6,%7}, {%8,%9}, {%0,%1,%2,%3};"
                        : "+f"(acc[mf][nf][0]), "+f"(acc[mf][nf][1]),
                          "+f"(acc[mf][nf][2]), "+f"(acc[mf][nf][3])
                        : "r"(a[mf][0]), "r"(a[mf][1]), "r"(a[mf][2]), "r"(a[mf][3]),
                          "r"(b[p][lo]), "r"(b[p][lo + 2]));
                }
            }
        }
        __syncthreads();
    }

    // Epilogue ---------------------------------------------------------------
    const float INF = __uint_as_float(0x7F800000u);
    float colall[8][2], colsel[8][2];
#pragma unroll
    for (int nf = 0; nf < 8; nf++) { colall[nf][0] = colall[nf][1] = INF;
                                     colsel[nf][0] = colsel[nf][1] = INF; }

#pragma unroll
    for (int mf = 0; mf < 2; mf++) {
        int r0 = warp_m * 32 + mf * 16 + (lane >> 2);
        int r1 = r0 + 8;
        int gi0 = i0 + r0, gi1 = i0 + r1;
        int   lab0 = labels[gi0],  lab1 = labels[gi1];
        float sqi0 = g_sq[gi0],    sqi1 = g_sq[gi1];
        float dp0  = g_dap2[gi0],  dp1  = g_dap2[gi1];
        float ma0 = INF, ms0 = INF, ma1 = INF, ms1 = INF;

#pragma unroll
        for (int nf = 0; nf < 8; nf++) {
#pragma unroll
            for (int cc = 0; cc < 2; cc++) {
                int jloc = warp_n * 64 + nf * 8 + (lane & 3) * 2 + cc;
                float sqj = sqj_s[jloc];
                float dpj = dpj_s[jloc];
                int   lbj = labj_s[jloc];
                float d2a = fmaxf(sqi0 + sqj - 2.f * acc[mf][nf][cc], 0.f);
                float d2b = fmaxf(sqi1 + sqj - 2.f * acc[mf][nf][cc + 2], 0.f);
                if (lbj != lab0) {
                    ma0 = fminf(ma0, d2a);
                    if (d2a > dp0) ms0 = fminf(ms0, d2a);
                    colall[nf][cc] = fminf(colall[nf][cc], d2a);
                    if (d2a > dpj) colsel[nf][cc] = fminf(colsel[nf][cc], d2a);
                }
                if (lbj != lab1) {
                    ma1 = fminf(ma1, d2b);
                    if (d2b > dp1) ms1 = fminf(ms1, d2b);
                    colall[nf][cc] = fminf(colall[nf][cc], d2b);
                    if (d2b > dpj) colsel[nf][cc] = fminf(colsel[nf][cc], d2b);
                }
            }
        }
#pragma unroll
        for (int m = 1; m < 4; m <<= 1) {
            ma0 = fminf(ma0, __shfl_xor_sync(0xffffffffu, ma0, m));
            ms0 = fminf(ms0, __shfl_xor_sync(0xffffffffu, ms0, m));
            ma1 = fminf(ma1, __shfl_xor_sync(0xffffffffu, ma1, m));
            ms1 = fminf(ms1, __shfl_xor_sync(0xffffffffu, ms1, m));
        }
        if ((lane & 3) == 0) {
            atomicMin(&g_min_all[gi0], __float_as_uint(ma0));
            atomicMin(&g_min_sel[gi0], __float_as_uint(ms0));
            atomicMin(&g_min_all[gi1], __float_as_uint(ma1));
            atomicMin(&g_min_sel[gi1], __float_as_uint(ms1));
        }
    }

#pragma unroll
    for (int nf = 0; nf < 8; nf++)
#pragma unroll
        for (int cc = 0; cc < 2; cc++) {
#pragma unroll
            for (int m = 4; m < 32; m <<= 1) {
                colall[nf][cc] = fminf(colall[nf][cc], __shfl_xor_sync(0xffffffffu, colall[nf][cc], m));
                colsel[nf][cc] = fminf(colsel[nf][cc], __shfl_xor_sync(0xffffffffu, colsel[nf][cc], m));
            }
        }
    if (lane < 4) {
#pragma unroll
        for (int nf = 0; nf < 8; nf++)
#pragma unroll
            for (int cc = 0; cc < 2; cc++) {
                int gj = j0 + warp_n * 64 + nf * 8 + lane * 2 + cc;
                atomicMin(&g_min_all[gj], __float_as_uint(colall[nf][cc]));
                atomicMin(&g_min_sel[gj], __float_as_uint(colsel[nf][cc]));
            }
    }
}

// ---------------------------------------------------------------------------
__global__ void finalize_kernel(float* __restrict__ out) {
    __shared__ float red[256];
    float s = 0.f;
    for (int i = threadIdx.x; i < BDIM; i += 256) {
        float ms   = __uint_as_float(g_min_sel[i]);
        float ma   = __uint_as_float(g_min_all[i]);
        float dan2 = isinf(ms) ? ma : ms;
        float dan  = sqrtf(dan2);
        float l    = g_dap[i] - dan + MARGIN;
        s += (l > 0.f) ? l : 0.f;
    }
    red[threadIdx.x] = s;
    __syncthreads();
#pragma unroll
    for (int stride = 128; stride > 0; stride >>= 1) {
        if (threadIdx.x < stride) red[threadIdx.x] += red[threadIdx.x + stride];
        __syncthreads();
    }
    if (threadIdx.x == 0) out[0] = red[0] / (float)BDIM;
}

// ---------------------------------------------------------------------------
extern "C" void kernel_launch(void* const* d_in, const int* in_sizes, int n_in,
                              void* d_out, int out_size) {
    const float* anchor   = (const float*)d_in[0];
    const float* positive = (const float*)d_in[1];
    const int*   labels   = (const int*)d_in[2];
    float*       out      = (float*)d_out;

    cudaFuncSetAttribute(tile_kernel, cudaFuncAttributeMaxDynamicSharedMemorySize, DYN_SMEM);

    row_stats_kernel<<<BDIM / 16, 512>>>(anchor, positive);
    tile_kernel<<<NBLK, 256, DYN_SMEM>>>(labels);
    finalize_kernel<<<1, 256>>>(out);
}

// round 8
// speedup vs baseline: 6.9220x; 1.1020x over previous
#include <cuda_runtime.h>
#include <cuda_bf16.h>
#include <math.h>
#include <stdint.h>

#define BDIM 4096
#define DDIM 512
#define MARGIN 0.2f

#define NTILE   32
#define NBLK    (NTILE * (NTILE + 1) / 2)  // 528
#define NSTEPS  (DDIM / 32)                // 16
#define STAGE_BYTES 16384                  // A(8K) + B(8K)
#define DYN_SMEM (4 * STAGE_BYTES)         // 64KB, 4 stages

// ---------------------------------------------------------------------------
__device__ float          g_sq[BDIM];
__device__ float          g_dap[BDIM];
__device__ float          g_dap2[BDIM];
__device__ unsigned int   g_min_sel[BDIM];
__device__ unsigned int   g_min_all[BDIM];
__device__ __nv_bfloat16  g_abf[BDIM * DDIM];

__device__ __forceinline__ uint32_t smem_u32(const void* p) {
    uint32_t a;
    asm("{ .reg .u64 t; cvta.to.shared.u64 t, %1; cvt.u32.u64 %0, t; }" : "=r"(a) : "l"(p));
    return a;
}

// Conflict-free layout: 2 logical rows per 128B line; chunk (0..7) XOR line.
__device__ __forceinline__ uint32_t sw_off(int row, int kc) {
    int line  = row >> 1;
    int chunk = (((row & 1) << 2) | kc) ^ (line & 7);
    return (uint32_t)(line * 128 + chunk * 16);
}

// ---------------------------------------------------------------------------
// Kernel A: per-row stats + init minima + bf16 conversion. One warp per row.
// ---------------------------------------------------------------------------
__global__ __launch_bounds__(512)
void row_stats_kernel(const float* __restrict__ anchor,
                      const float* __restrict__ positive) {
    int warp = threadIdx.x >> 5;
    int lane = threadIdx.x & 31;
    int row  = blockIdx.x * 16 + warp;
    const float* a = anchor   + (size_t)row * DDIM;
    const float* p = positive + (size_t)row * DDIM;

    float s_sq = 0.f, s_ap = 0.f;
#pragma unroll
    for (int c = lane * 4; c < DDIM; c += 128) {
        float4 av = *reinterpret_cast<const float4*>(a + c);
        float4 pv = *reinterpret_cast<const float4*>(p + c);
        s_sq += av.x * av.x + av.y * av.y + av.z * av.z + av.w * av.w;
        float dx = av.x - pv.x, dy = av.y - pv.y, dz = av.z - pv.z, dw = av.w - pv.w;
        s_ap += dx * dx + dy * dy + dz * dz + dw * dw;
        __nv_bfloat162 b0 = __floats2bfloat162_rn(av.x, av.y);
        __nv_bfloat162 b1 = __floats2bfloat162_rn(av.z, av.w);
        uint2 packed = make_uint2(*reinterpret_cast<uint32_t*>(&b0),
                                  *reinterpret_cast<uint32_t*>(&b1));
        *reinterpret_cast<uint2*>(&g_abf[(size_t)row * DDIM + c]) = packed;
    }
#pragma unroll
    for (int m = 16; m > 0; m >>= 1) {
        s_sq += __shfl_xor_sync(0xffffffffu, s_sq, m);
        s_ap += __shfl_xor_sync(0xffffffffu, s_ap, m);
    }
    if (lane == 0) {
        g_sq[row]      = s_sq;
        g_dap[row]     = s_ap;
        g_dap2[row]    = s_ap * s_ap;
        g_min_sel[row] = 0x7F800000u;
        g_min_all[row] = 0x7F800000u;
    }
}

// ---------------------------------------------------------------------------
// Kernel B: symmetric bf16 HMMA Gram tile (128x128x512), upper triangle only,
// fused row+column masked-min epilogue. 256 thr / 8 warps; warp tile 32x64.
// BK=32, 4-stage cp.async ring, ONE barrier per iteration, fully unrolled.
// ---------------------------------------------------------------------------
__global__ __launch_bounds__(256, 2)
void tile_kernel(const int* __restrict__ labels) {
    extern __shared__ __align__(1024) char dsm[];
    __shared__ float sqj_s[128];
    __shared__ float dpj_s[128];
    __shared__ int   labj_s[128];

    const int tid    = threadIdx.x;
    const int wid    = tid >> 5;
    const int lane   = tid & 31;
    const int warp_m = wid & 3;
    const int warp_n = wid >> 2;

    int t = blockIdx.x;
    int bi = 0;
    {
        int rem = t;
        while (rem >= NTILE - bi) { rem -= NTILE - bi; bi++; }
        t = bi + rem;
    }
    const int bj = t;
    const int i0 = bi * 128;
    const int j0 = bj * 128;

    if (tid < 128) {
        sqj_s[tid]  = g_sq[j0 + tid];
        dpj_s[tid]  = g_dap2[j0 + tid];
        labj_s[tid] = labels[j0 + tid];
    }

    const uint32_t dsm_u = smem_u32(dsm);
    const int ld_row = tid >> 1;
    const int ld_kc0 = (tid & 1) * 2;

    auto issue_loads = [&](int stage, int k0) {
        const __nv_bfloat16* srcA = g_abf + (size_t)(i0 + ld_row) * DDIM + k0;
        const __nv_bfloat16* srcB = g_abf + (size_t)(j0 + ld_row) * DDIM + k0;
        uint32_t sbase = dsm_u + stage * STAGE_BYTES;
#pragma unroll
        for (int l = 0; l < 2; l++) {
            int kc = ld_kc0 + l;
            uint32_t off = sw_off(ld_row, kc);
            asm volatile("cp.async.cg.shared.global [%0], [%1], 16;"
                         :: "r"(sbase + off), "l"(srcA + kc * 8) : "memory");
            asm volatile("cp.async.cg.shared.global [%0], [%1], 16;"
                         :: "r"(sbase + 8192 + off), "l"(srcB + kc * 8) : "memory");
        }
        asm volatile("cp.async.commit_group;" ::: "memory");
    };

    float acc[2][8][4];
#pragma unroll
    for (int mf = 0; mf < 2; mf++)
#pragma unroll
        for (int nf = 0; nf < 8; nf++)
#pragma unroll
            for (int c = 0; c < 4; c++) acc[mf][nf][c] = 0.f;

    issue_loads(0, 0);
    issue_loads(1, 32);
    issue_loads(2, 64);

#pragma unroll
    for (int it = 0; it < NSTEPS; it++) {
        const int buf = it & 3;
        if (it < NSTEPS - 2)       asm volatile("cp.async.wait_group 2;" ::: "memory");
        else if (it == NSTEPS - 2) asm volatile("cp.async.wait_group 1;" ::: "memory");
        else                       asm volatile("cp.async.wait_group 0;" ::: "memory");
        // Single barrier per iteration: also protects stage (it+3)&3 against
        // stragglers still reading it as stage (it-1)&3.
        __syncthreads();
        if (it + 3 < NSTEPS) issue_loads((it + 3) & 3, (it + 3) * 32);

        const uint32_t a_base = dsm_u + buf * STAGE_BYTES;
        const uint32_t b_base = a_base + 8192;
#pragma unroll
        for (int s = 0; s < 2; s++) {
            const int kc = 2 * s + (lane >> 4);
            uint32_t a[2][4];
#pragma unroll
            for (int mf = 0; mf < 2; mf++) {
                int row = warp_m * 32 + mf * 16 + ((lane >> 3) & 1) * 8 + (lane & 7);
                uint32_t addr = a_base + sw_off(row, kc);
                asm volatile("ldmatrix.sync.aligned.m8n8.x4.shared.b16 {%0,%1,%2,%3}, [%4];"
                             : "=r"(a[mf][0]), "=r"(a[mf][1]), "=r"(a[mf][2]), "=r"(a[mf][3])
                             : "r"(addr));
            }
            uint32_t b[4][4];
#pragma unroll
            for (int p = 0; p < 4; p++) {
                int row = warp_n * 64 + p * 16 + ((lane >> 3) & 1) * 8 + (lane & 7);
                uint32_t addr = b_base + sw_off(row, kc);
                asm volatile("ldmatrix.sync.aligned.m8n8.x4.shared.b16 {%0,%1,%2,%3}, [%4];"
                             : "=r"(b[p][0]), "=r"(b[p][1]), "=r"(b[p][2]), "=r"(b[p][3])
                             : "r"(addr));
            }
#pragma unroll
            for (int mf = 0; mf < 2; mf++) {
#pragma unroll
                for (int nf = 0; nf < 8; nf++) {
                    int p  = nf >> 1;
                    int lo = (nf & 1);
                    asm volatile(
                        "mma.sync.aligned.m16n8k16.row.col.f32.bf16.bf16.f32 "
                        "{%0,%1,%2,%3}, {%4,%5,%6,%7}, {%8,%9}, {%0,%1,%2,%3};"
                        : "+f"(acc[mf][nf][0]), "+f"(acc[mf][nf][1]),
                          "+f"(acc[mf][nf][2]), "+f"(acc[mf][nf][3])
                        : "r"(a[mf][0]), "r"(a[mf][1]), "r"(a[mf][2]), "r"(a[mf][3]),
                          "r"(b[p][lo]), "r"(b[p][lo + 2]));
                }
            }
        }
    }

    // Epilogue ---------------------------------------------------------------
    const float INF = __uint_as_float(0x7F800000u);
    float colall[8][2], colsel[8][2];
#pragma unroll
    for (int nf = 0; nf < 8; nf++) { colall[nf][0] = colall[nf][1] = INF;
                                     colsel[nf][0] = colsel[nf][1] = INF; }

#pragma unroll
    for (int mf = 0; mf < 2; mf++) {
        int r0 = warp_m * 32 + mf * 16 + (lane >> 2);
        int r1 = r0 + 8;
        int gi0 = i0 + r0, gi1 = i0 + r1;
        int   lab0 = labels[gi0],  lab1 = labels[gi1];
        float sqi0 = g_sq[gi0],    sqi1 = g_sq[gi1];
        float dp0  = g_dap2[gi0],  dp1  = g_dap2[gi1];
        float ma0 = INF, ms0 = INF, ma1 = INF, ms1 = INF;

#pragma unroll
        for (int nf = 0; nf < 8; nf++) {
#pragma unroll
            for (int cc = 0; cc < 2; cc++) {
                int jloc = warp_n * 64 + nf * 8 + (lane & 3) * 2 + cc;
                float sqj = sqj_s[jloc];
                float dpj = dpj_s[jloc];
                int   lbj = labj_s[jloc];
                float d2a = fmaxf(sqi0 + sqj - 2.f * acc[mf][nf][cc], 0.f);
                float d2b = fmaxf(sqi1 + sqj - 2.f * acc[mf][nf][cc + 2], 0.f);
                if (lbj != lab0) {
                    ma0 = fminf(ma0, d2a);
                    if (d2a > dp0) ms0 = fminf(ms0, d2a);
                    colall[nf][cc] = fminf(colall[nf][cc], d2a);
                    if (d2a > dpj) colsel[nf][cc] = fminf(colsel[nf][cc], d2a);
                }
                if (lbj != lab1) {
                    ma1 = fminf(ma1, d2b);
                    if (d2b > dp1) ms1 = fminf(ms1, d2b);
                    colall[nf][cc] = fminf(colall[nf][cc], d2b);
                    if (d2b > dpj) colsel[nf][cc] = fminf(colsel[nf][cc], d2b);
                }
            }
        }
#pragma unroll
        for (int m = 1; m < 4; m <<= 1) {
            ma0 = fminf(ma0, __shfl_xor_sync(0xffffffffu, ma0, m));
            ms0 = fminf(ms0, __shfl_xor_sync(0xffffffffu, ms0, m));
            ma1 = fminf(ma1, __shfl_xor_sync(0xffffffffu, ma1, m));
            ms1 = fminf(ms1, __shfl_xor_sync(0xffffffffu, ms1, m));
        }
        if ((lane & 3) == 0) {
            atomicMin(&g_min_all[gi0], __float_as_uint(ma0));
            atomicMin(&g_min_sel[gi0], __float_as_uint(ms0));
            atomicMin(&g_min_all[gi1], __float_as_uint(ma1));
            atomicMin(&g_min_sel[gi1], __float_as_uint(ms1));
        }
    }

#pragma unroll
    for (int nf = 0; nf < 8; nf++)
#pragma unroll
        for (int cc = 0; cc < 2; cc++) {
#pragma unroll
            for (int m = 4; m < 32; m <<= 1) {
                colall[nf][cc] = fminf(colall[nf][cc], __shfl_xor_sync(0xffffffffu, colall[nf][cc], m));
                colsel[nf][cc] = fminf(colsel[nf][cc], __shfl_xor_sync(0xffffffffu, colsel[nf][cc], m));
            }
        }
    if (lane < 4) {
#pragma unroll
        for (int nf = 0; nf < 8; nf++)
#pragma unroll
            for (int cc = 0; cc < 2; cc++) {
                int gj = j0 + warp_n * 64 + nf * 8 + lane * 2 + cc;
                atomicMin(&g_min_all[gj], __float_as_uint(colall[nf][cc]));
                atomicMin(&g_min_sel[gj], __float_as_uint(colsel[nf][cc]));
            }
    }
}

// ---------------------------------------------------------------------------
__global__ void finalize_kernel(float* __restrict__ out) {
    __shared__ float red[256];
    float s = 0.f;
    for (int i = threadIdx.x; i < BDIM; i += 256) {
        float ms   = __uint_as_float(g_min_sel[i]);
        float ma   = __uint_as_float(g_min_all[i]);
        float dan2 = isinf(ms) ? ma : ms;
        float dan  = sqrtf(dan2);
        float l    = g_dap[i] - dan + MARGIN;
        s += (l > 0.f) ? l : 0.f;
    }
    red[threadIdx.x] = s;
    __syncthreads();
#pragma unroll
    for (int stride = 128; stride > 0; stride >>= 1) {
        if (threadIdx.x < stride) red[threadIdx.x] += red[threadIdx.x + stride];
        __syncthreads();
    }
    if (threadIdx.x == 0) out[0] = red[0] / (float)BDIM;
}

// ---------------------------------------------------------------------------
extern "C" void kernel_launch(void* const* d_in, const int* in_sizes, int n_in,
                              void* d_out, int out_size) {
    const float* anchor   = (const float*)d_in[0];
    const float* positive = (const float*)d_in[1];
    const int*   labels   = (const int*)d_in[2];
    float*       out      = (float*)d_out;

    cudaFuncSetAttribute(tile_kernel, cudaFuncAttributeMaxDynamicSharedMemorySize, DYN_SMEM);

    row_stats_kernel<<<BDIM / 16, 512>>>(anchor, positive);
    tile_kernel<<<NBLK, 256, DYN_SMEM>>>(labels);
    finalize_kernel<<<1, 256>>>(out);
}